// round 9
// baseline (speedup 1.0000x reference)
#include <cuda_runtime.h>
#include <cuda_bf16.h>

// Problem constants (fixed by the reference: B=4096, N=256, K=16)
#define NN   256
#define KK   16
#define PP   32640           // N*(N-1)/2
#define BB   4096
#define TPB  256             // threads per block
#define NG   2               // groups of 4 pairs per thread -> 8 pairs/thread
#define TILE (TPB * NG * 4)  // 2048 pairs per block tile
#define GX   16              // p-tiles: 16*2048 = 32768 >= 32640
#define GY   128             // batch stripes: each block loops 4096/128 = 32 rows

// pstart(i) = number of pairs before row i = i*(N-1) - i*(i-1)/2
__device__ __forceinline__ int pstart(int i) {
    return i * (NN - 1) - (i * (i - 1)) / 2;
}

// invert triangular index p -> (i, j)
__device__ __forceinline__ void inv_tri(int pc, int& io, int& jo) {
    float disc = 2.0f * NN - 1.0f;       // 511
    int i = (int)floorf((disc - sqrtf(disc * disc - 8.0f * (float)pc)) * 0.5f);
    if (i < 0) i = 0;
    if (i > NN - 2) i = NN - 2;
    while (i < NN - 2 && pstart(i + 1) <= pc) i++;
    while (i > 0 && pstart(i) > pc) i--;
    io = i;
    jo = i + 1 + (pc - pstart(i));
}

__global__ void __launch_bounds__(TPB)
cross_utpm_kernel(const float* __restrict__ x,
                  const float* __restrict__ L,
                  float* __restrict__ out)
{
    // 4 shift-copies of the current x row: S[r*NN + m] = x[b, m + r]
    __shared__ __align__(16) float S[4 * NN];

    const int t  = threadIdx.x;
    const int p0 = blockIdx.x * TILE;

    // ---- one-time per-thread setup (b-invariant) ----
    int   ii[NG][4];
    int   jj[NG][4];
    float sp[NG][4];
    int   soff[NG];          // flat offset into S for the aligned LDS.128 fast path
    bool  val[NG];
    bool  uni[NG];

#pragma unroll
    for (int g = 0; g < NG; g++) {
        int pg = p0 + (g * TPB + t) * 4;     // group base pair (mult of 4)
        val[g] = (pg < PP);                  // PP % 4 == 0 -> groups fully valid/invalid
        int base = val[g] ? pg : 0;

#pragma unroll
        for (int k = 0; k < 4; k++) {
            int i, j;
            inv_tri(base + k, i, j);
            ii[g][k] = i;
            jj[g][k] = j;
            float s = 0.0f;
#pragma unroll
            for (int kk = 0; kk < KK; kk++)
                s += L[i * KK + kk] * L[j * KK + kk];
            sp[g][k] = s;
        }
        uni[g] = (ii[g][0] == ii[g][3]);     // all 4 pairs in same row i
        int j0 = jj[g][0];
        int r  = j0 & 3;
        soff[g] = r * NN + (j0 & ~3);        // S[r][j0 - r] -> 16B aligned
    }

    // ---- main loop over batch rows (strided by GY) ----
    for (int b = blockIdx.y; b < BB; b += GY) {
        __syncthreads();                      // protect S against previous readers
        float v = x[(size_t)b * NN + t];
        S[t] = v;                             // S[0][t]
        if (t >= 1) S[NN     + t - 1] = v;    // S[1][t-1] = x[t]
        if (t >= 2) S[2 * NN + t - 2] = v;
        if (t >= 3) S[3 * NN + t - 3] = v;
        __syncthreads();

        float* orow = out + (size_t)b * PP;
#pragma unroll
        for (int g = 0; g < NG; g++) {
            if (!val[g]) continue;
            int pg = p0 + (g * TPB + t) * 4;
            float4 r4;
            if (uni[g]) {
                float  xi = S[ii[g][0]];                          // broadcast LDS.32
                float4 xj = *reinterpret_cast<const float4*>(&S[soff[g]]); // LDS.128
                r4.x = xi * xj.x * sp[g][0];
                r4.y = xi * xj.y * sp[g][1];
                r4.z = xi * xj.z * sp[g][2];
                r4.w = xi * xj.w * sp[g][3];
            } else {
                // rare row-boundary group: scalar path
                r4.x = S[ii[g][0]] * S[jj[g][0]] * sp[g][0];
                r4.y = S[ii[g][1]] * S[jj[g][1]] * sp[g][1];
                r4.z = S[ii[g][2]] * S[jj[g][2]] * sp[g][2];
                r4.w = S[ii[g][3]] * S[jj[g][3]] * sp[g][3];
            }
            *reinterpret_cast<float4*>(orow + pg) = r4;           // STG.128, coalesced
        }
    }
}

extern "C" void kernel_launch(void* const* d_in, const int* in_sizes, int n_in,
                              void* d_out, int out_size)
{
    const float* x = (const float*)d_in[0];        // [4096, 256]
    const float* L = (const float*)d_in[1];        // [256, 16]
    float* out     = (float*)d_out;                // [4096, 32640]

    dim3 grid(GX, GY);
    cross_utpm_kernel<<<grid, TPB>>>(x, L, out);
}